// round 2
// baseline (speedup 1.0000x reference)
#include <cuda_runtime.h>
#include <math_constants.h>

// Problem dims (fixed)
#define Bv 4
#define Nv 256
#define Dv 128
#define Mv 128
#define Cv 128
#define ROWS (Bv * Nv)   // 1024

// Scratch (allocation-free: __device__ globals)
__device__ float g_pi[ROWS * Mv];     // h@W1a + b1
__device__ float g_pj[ROWS * Mv];     // h@W1b
__device__ float g_S [ROWS * Mv];     // masked adj-weighted silu sum
__device__ float g_amask[ROWS];       // sum_{j!=i} adj
__device__ float g_denom[ROWS];       // max(sum_j adj, 1)

// ---------------------------------------------------------------------------
// K1: pre-GEMM.  (1024 x 128) @ (128 x 256) where W = [W1a | W1b].
// 4 rows/block, 256 threads, thread computes 4 consecutive cols of 1 row.
// ---------------------------------------------------------------------------
__global__ void k_pre(const float* __restrict__ h,
                      const float* __restrict__ W1a,
                      const float* __restrict__ W1b,
                      const float* __restrict__ b1)
{
    __shared__ float sW[32][256];   // K-chunk of combined W
    __shared__ float sH[4][128];    // 4 rows of h

    const int row0 = blockIdx.x * 4;
    const int r    = threadIdx.x >> 6;          // 0..3
    const int c    = (threadIdx.x & 63) * 4;    // 0..252

    for (int idx = threadIdx.x; idx < 4 * 128; idx += 256)
        sH[idx >> 7][idx & 127] = h[(row0 + (idx >> 7)) * Dv + (idx & 127)];

    float acc0 = 0.f, acc1 = 0.f, acc2 = 0.f, acc3 = 0.f;

    for (int kk = 0; kk < Dv; kk += 32) {
        __syncthreads();
        for (int idx = threadIdx.x; idx < 32 * 256; idx += 256) {
            int k  = idx >> 8;
            int cc = idx & 255;
            sW[k][cc] = (cc < 128) ? W1a[(kk + k) * Mv + cc]
                                   : W1b[(kk + k) * Mv + (cc - 128)];
        }
        __syncthreads();
        #pragma unroll
        for (int k = 0; k < 32; ++k) {
            float hv = sH[r][kk + k];
            float4 w = *(const float4*)&sW[k][c];
            acc0 = fmaf(hv, w.x, acc0);
            acc1 = fmaf(hv, w.y, acc1);
            acc2 = fmaf(hv, w.z, acc2);
            acc3 = fmaf(hv, w.w, acc3);
        }
    }

    const int row = row0 + r;
    if (c < 128) {
        g_pi[row * Mv + c + 0] = acc0 + b1[c + 0];
        g_pi[row * Mv + c + 1] = acc1 + b1[c + 1];
        g_pi[row * Mv + c + 2] = acc2 + b1[c + 2];
        g_pi[row * Mv + c + 3] = acc3 + b1[c + 3];
    } else {
        const int cm = c - 128;
        g_pj[row * Mv + cm + 0] = acc0;
        g_pj[row * Mv + cm + 1] = acc1;
        g_pj[row * Mv + cm + 2] = acc2;
        g_pj[row * Mv + cm + 3] = acc3;
    }
}

// ---------------------------------------------------------------------------
// K2: main pairwise loop.  One block = (b, i0..i0+3), 512 threads.
// thread -> (i_local = tid/128, m = tid%128).  Loops j = 0..255:
//   acc += adj[b,i,j] * silu(pi[b,i,m] + pj[b,j,m])        (j != i)
// Also computes adj row sums (denom / masked sum) per i.
// ---------------------------------------------------------------------------
__global__ void k_main(const float* __restrict__ adj)
{
    __shared__ float red[512];

    const int b    = blockIdx.x >> 6;          // /64
    const int i0   = (blockIdx.x & 63) << 2;
    const int il   = threadIdx.x >> 7;
    const int m    = threadIdx.x & 127;
    const int i    = i0 + il;
    const int rowA = b * Nv + i;
    const float* __restrict__ adjr = adj + (size_t)rowA * Nv;

    // --- adj row reduction (denom & masked sum) ---
    red[threadIdx.x] = adjr[m] + adjr[m + 128];
    __syncthreads();
    for (int s = 64; s > 0; s >>= 1) {
        if (m < s) red[threadIdx.x] += red[threadIdx.x + s];
        __syncthreads();
    }
    if (m == 0) {
        float rs = red[il << 7];
        g_denom[rowA] = fmaxf(rs, 1.0f);
        g_amask[rowA] = rs - adjr[i];
    }

    // --- pairwise silu accumulation ---
    const float piv = g_pi[rowA * Mv + m];
    const float* __restrict__ pjb = g_pj + (size_t)(b * Nv) * Mv + m;

    float acc = 0.f;
    #pragma unroll 4
    for (int j = 0; j < Nv; ++j) {
        float pjv = __ldg(pjb + j * Mv);
        float a   = __ldg(adjr + j);
        if (j == i) a = 0.f;
        float x   = piv + pjv;
        float e   = __expf(-x);
        float sig = __fdividef(1.0f, 1.0f + e);
        acc = fmaf(a, x * sig, acc);
    }
    g_S[rowA * Mv + m] = acc;
}

// ---------------------------------------------------------------------------
// K3: fused epilogue.  8 rows/block, 256 threads.
//   m_agg = (S @ W2 + b2*amask) / denom
//   t     = silu(m_agg @ Wc1 + bc1)
//   out   = t @ Wc2 + bc2
// Weights staged in 32-row K-chunks through one 16 KB smem buffer.
// ---------------------------------------------------------------------------
__device__ __forceinline__ void gemm8x128(const float* __restrict__ W,
                                          const float (*in)[128],
                                          float sW[32][128],
                                          int r, int c, float acc[4])
{
    acc[0] = acc[1] = acc[2] = acc[3] = 0.f;
    for (int kk = 0; kk < Mv; kk += 32) {
        __syncthreads();
        for (int idx = threadIdx.x; idx < 32 * 128; idx += 256)
            sW[idx >> 7][idx & 127] = W[(kk + (idx >> 7)) * Mv + (idx & 127)];
        __syncthreads();
        #pragma unroll
        for (int k = 0; k < 32; ++k) {
            float av = in[r][kk + k];
            float4 w = *(const float4*)&sW[k][c];
            acc[0] = fmaf(av, w.x, acc[0]);
            acc[1] = fmaf(av, w.y, acc[1]);
            acc[2] = fmaf(av, w.z, acc[2]);
            acc[3] = fmaf(av, w.w, acc[3]);
        }
    }
}

__global__ void k_post(const float* __restrict__ W2,  const float* __restrict__ b2,
                       const float* __restrict__ Wc1, const float* __restrict__ bc1,
                       const float* __restrict__ Wc2, const float* __restrict__ bc2,
                       float* __restrict__ out)
{
    __shared__ float sW[32][128];
    __shared__ float bufA[8][128];
    __shared__ float bufB[8][128];

    const int row0 = blockIdx.x * 8;
    const int r    = threadIdx.x >> 5;          // 0..7
    const int c    = (threadIdx.x & 31) * 4;    // 0..124
    const int row  = row0 + r;

    for (int idx = threadIdx.x; idx < 8 * 128; idx += 256)
        bufA[idx >> 7][idx & 127] = g_S[(row0 + (idx >> 7)) * Mv + (idx & 127)];
    // first __syncthreads inside gemm8x128 orders these stores

    float acc[4];

    // Phase A: m_agg
    gemm8x128(W2, bufA, sW, r, c, acc);
    {
        float am  = g_amask[row];
        float inv = __fdividef(1.0f, g_denom[row]);
        #pragma unroll
        for (int t = 0; t < 4; ++t)
            bufB[r][c + t] = (acc[t] + b2[c + t] * am) * inv;
    }
    __syncthreads();

    // Phase B: silu(m_agg @ Wc1 + bc1)
    gemm8x128(Wc1, bufB, sW, r, c, acc);
    {
        #pragma unroll
        for (int t = 0; t < 4; ++t) {
            float u = acc[t] + bc1[c + t];
            float e = __expf(-u);
            bufA[r][c + t] = __fdividef(u, 1.0f + e);
        }
    }
    __syncthreads();

    // Phase C: out = t @ Wc2 + bc2
    gemm8x128(Wc2, bufA, sW, r, c, acc);
    #pragma unroll
    for (int t = 0; t < 4; ++t)
        out[row * Cv + c + t] = acc[t] + bc2[c + t];
}

// ---------------------------------------------------------------------------
// Launch.  Inputs (metadata order):
//  0:h 1:adj 2:W1a 3:W1b 4:b1 5:W2 6:b2 7:Wc1 8:bc1 9:Wc2 10:bc2
// ---------------------------------------------------------------------------
extern "C" void kernel_launch(void* const* d_in, const int* in_sizes, int n_in,
                              void* d_out, int out_size)
{
    (void)in_sizes; (void)n_in; (void)out_size;
    const float* h   = (const float*)d_in[0];
    const float* adj = (const float*)d_in[1];
    const float* W1a = (const float*)d_in[2];
    const float* W1b = (const float*)d_in[3];
    const float* b1  = (const float*)d_in[4];
    const float* W2  = (const float*)d_in[5];
    const float* b2  = (const float*)d_in[6];
    const float* Wc1 = (const float*)d_in[7];
    const float* bc1 = (const float*)d_in[8];
    const float* Wc2 = (const float*)d_in[9];
    const float* bc2 = (const float*)d_in[10];
    float* out = (float*)d_out;

    k_pre <<<ROWS / 4, 256>>>(h, W1a, W1b, b1);
    k_main<<<ROWS / 4, 512>>>(adj);
    k_post<<<ROWS / 8, 256>>>(W2, b2, Wc1, bc1, Wc2, bc2, out);
}